// round 13
// baseline (speedup 1.0000x reference)
#include <cuda_runtime.h>
#include <cuda_bf16.h>
#include <cstdint>
#include <math.h>

#define BB 2
#define HH 16
#define SQ 2048
#define DDIM 64
#define MQ 128
#define NTH 256
#define C_SCALE 0.18033688011110543f   // 0.125 * log2(e)

// smem layout (u32 units)
#define U_KH 0                 // pass2: [2][2048]; pass1: bufs [2][4096]; tail: scan+mask
#define U_KL 4096
#define U_VH 8192
#define U_VL 12288
#define SMEM_BYTES (16384 * 4)

// global scratch
__device__ uint32_t g_KH[32 * 16 * 4096];
__device__ uint32_t g_KL[32 * 16 * 4096];
__device__ uint32_t g_VH[32 * 16 * 4096];
__device__ uint32_t g_VL[32 * 16 * 4096];
__device__ int g_idx[BB][SQ];
__device__ int g_scan[BB][SQ];
__device__ int g_N[BB];
__device__ float g_Wc[(size_t)BB * HH * SQ * SQ];   // compact weights (512 MB)

static __device__ __forceinline__ uint32_t smem_u32(const void* p) {
    uint32_t a;
    asm("{ .reg .u64 t; cvta.to.shared.u64 t, %1; cvt.u32.u64 %0, t; }" : "=r"(a) : "l"(p));
    return a;
}
static __device__ __forceinline__ void cp16(uint32_t dst, const void* src) {
    asm volatile("cp.async.cg.shared.global [%0], [%1], 16;" :: "r"(dst), "l"(src));
}
#define CP_COMMIT() asm volatile("cp.async.commit_group;" ::: "memory")
#define CP_WAIT0()  asm volatile("cp.async.wait_group 0;" ::: "memory")

static __device__ __forceinline__ float ex2f(float x) {
    float y; asm("ex2.approx.f32 %0, %1;" : "=f"(y) : "f"(x)); return y;
}
static __device__ __forceinline__ float lg2f(float x) {
    float y; asm("lg2.approx.f32 %0, %1;" : "=f"(y) : "f"(x)); return y;
}

static __device__ __forceinline__ void mma_bf16(float* c, const uint32_t* a, const uint32_t* b) {
    asm volatile(
        "mma.sync.aligned.m16n8k16.row.col.f32.bf16.bf16.f32 "
        "{%0,%1,%2,%3}, {%4,%5,%6,%7}, {%8,%9}, {%0,%1,%2,%3};"
        : "+f"(c[0]), "+f"(c[1]), "+f"(c[2]), "+f"(c[3])
        : "r"(a[0]), "r"(a[1]), "r"(a[2]), "r"(a[3]), "r"(b[0]), "r"(b[1]));
}

static __device__ __forceinline__ void split2(float a, float b, uint32_t& hi, uint32_t& lo) {
    __nv_bfloat162 h = __floats2bfloat162_rn(a, b);
    float ra = a - __bfloat162float(__low2bfloat16(h));
    float rb = b - __bfloat162float(__high2bfloat16(h));
    __nv_bfloat162 l = __floats2bfloat162_rn(ra, rb);
    hi = *reinterpret_cast<uint32_t*>(&h);
    lo = *reinterpret_cast<uint32_t*>(&l);
}

// ---------- prep A: compacted key index + exclusive scan per batch ----------
__global__ __launch_bounds__(1024)
void prep_index(const int* __restrict__ M) {
    const int b = blockIdx.x;
    const int t = threadIdx.x;
    __shared__ int a[1024];
    int m0 = M[b * SQ + 2 * t];
    int m1 = M[b * SQ + 2 * t + 1];
    a[t] = m0 + m1;
    __syncthreads();
    for (int off = 1; off < 1024; off <<= 1) {
        int v = a[t];
        if (t >= off) v += a[t - off];
        __syncthreads();
        a[t] = v;
        __syncthreads();
    }
    int total = a[1023];
    int excl = a[t] - (m0 + m1);
    g_scan[b][2 * t]     = excl;
    g_scan[b][2 * t + 1] = excl + m0;
    if (m0) g_idx[b][excl] = 2 * t;
    if (m1) g_idx[b][excl + m0] = 2 * t + 1;
    for (int i = t; i < SQ; i += 1024)
        if (i >= total) g_idx[b][i] = -1;
    if (t == 0) g_N[b] = total;
}

// ---------- prep B: gather+split compacted K/V into frag-native scratch ----------
__global__ __launch_bounds__(1024)
void prep_split(const float* __restrict__ K, const float* __restrict__ V) {
    const int tile = blockIdx.x;                // bh*16 + compact 128-key tile
    const int bh = tile >> 4;
    const int b  = bh / HH;
    const int tloc = tile & 15;
    const int t = threadIdx.x;
    if (blockIdx.y == 0) {
        uint32_t* dH = g_KH + (size_t)tile * 4096;
        uint32_t* dL = g_KL + (size_t)tile * 4096;
        #pragma unroll
        for (int i = 0; i < 4; i++) {
            int idx = i * 1024 + t;
            int key = idx >> 5, dp = idx & 31;
            int orig = g_idx[b][tloc * 128 + key];
            float2 x = make_float2(0.f, 0.f);
            if (orig >= 0)
                x = ((const float2*)(K + ((size_t)bh * SQ + orig) * DDIM))[dp];
            int slot = (key >> 3) * 256 + (dp >> 3) * 64
                     + ((key & 7) * 4 + (dp & 3)) * 2 + ((dp >> 2) & 1);
            uint32_t hi, lo; split2(x.x, x.y, hi, lo);
            dH[slot] = hi; dL[slot] = lo;
        }
    } else {
        uint32_t* dH = g_VH + (size_t)tile * 4096;
        uint32_t* dL = g_VL + (size_t)tile * 4096;
        #pragma unroll
        for (int i = 0; i < 4; i++) {
            int idx = i * 1024 + t;
            int d = idx & 63, kp = idx >> 6;
            int o0 = g_idx[b][tloc * 128 + 2 * kp];
            int o1 = g_idx[b][tloc * 128 + 2 * kp + 1];
            float va = (o0 >= 0) ? V[((size_t)bh * SQ + o0) * DDIM + d] : 0.f;
            float vb = (o1 >= 0) ? V[((size_t)bh * SQ + o1) * DDIM + d] : 0.f;
            int kc2 = kp >> 3, w8 = kp & 7;
            int slot = kc2 * 512 + (d >> 3) * 64
                     + ((d & 7) * 4 + (w8 & 3)) * 2 + (w8 >> 2);
            uint32_t hi, lo; split2(va, vb, hi, lo);
            dH[slot] = hi; dL[slot] = lo;
        }
    }
}

// ---------- main: compact compute -> Wc, then dense coalesced expansion ----------
__global__ __launch_bounds__(NTH, 2)
void attn13(const float* __restrict__ Q, const int* __restrict__ M,
            float* __restrict__ Out, float* __restrict__ W) {
    extern __shared__ __align__(16) uint32_t smu[];
    const uint32_t sb = smem_u32(smu);

    const int t    = threadIdx.x;
    const int lane = t & 31;
    const int wid  = t >> 5;
    const int g    = lane >> 2;
    const int t4   = lane & 3;
    const int dlo  = 2 * t4;
    const int qb   = wid * 16;

    const int qt = blockIdx.x;
    const int bh = blockIdx.y;
    const int b  = bh / HH;

    const float* qg = Q + ((size_t)bh * SQ + (size_t)qt * MQ) * DDIM;
    const int N = g_N[b];
    const int nt1 = (N + 127) >> 7;
    const int nt2 = (N + 63) >> 6;

    auto pfK1 = [&](int buf, int bt) {
        const uint32_t* sH = g_KH + ((size_t)bh * 16 + bt) * 4096;
        const uint32_t d = sb + (uint32_t)buf * 4096 * 4;
        #pragma unroll
        for (int c = 0; c < 4; c++) {
            int o = (c * NTH + t) * 4;
            cp16(d + o * 4, sH + o);
        }
    };
    auto pfK = [&](int buf, int kt64) {
        const size_t off = ((size_t)bh * 16 + (kt64 >> 1)) * 4096 + (size_t)(kt64 & 1) * 2048;
        const uint32_t dH = sb + (U_KH + buf * 2048) * 4;
        const uint32_t dL = sb + (U_KL + buf * 2048) * 4;
        #pragma unroll
        for (int c = 0; c < 2; c++) {
            int o = (c * NTH + t) * 4;
            cp16(dH + o * 4, g_KH + off + o);
            cp16(dL + o * 4, g_KL + off + o);
        }
    };
    auto pfV = [&](int buf, int kt64) {
        const size_t off = ((size_t)bh * 16 + (kt64 >> 1)) * 4096 + (size_t)(kt64 & 1) * 2048;
        const uint32_t dH = sb + (U_VH + buf * 2048) * 4;
        const uint32_t dL = sb + (U_VL + buf * 2048) * 4;
        #pragma unroll
        for (int c = 0; c < 2; c++) {
            int o = (c * NTH + t) * 4;
            cp16(dH + o * 4, g_VH + off + o);
            cp16(dL + o * 4, g_VL + off + o);
        }
    };

    pfK1(0, 0); CP_COMMIT();

    // ---- persistent Q A-fragments (hi/lo) ----
    uint32_t AH[4][4], AL[4][4];
    #pragma unroll
    for (int kc = 0; kc < 4; kc++) {
        const float* r0 = qg + (size_t)(qb + g) * DDIM + kc * 16 + dlo;
        const float* r1 = r0 + 8 * DDIM;
        float2 p0 = *(const float2*)(r0);
        float2 p1 = *(const float2*)(r1);
        float2 p2 = *(const float2*)(r0 + 8);
        float2 p3 = *(const float2*)(r1 + 8);
        split2(p0.x, p0.y, AH[kc][0], AL[kc][0]);
        split2(p1.x, p1.y, AH[kc][1], AL[kc][1]);
        split2(p2.x, p2.y, AH[kc][2], AL[kc][2]);
        split2(p3.x, p3.y, AH[kc][3], AL[kc][3]);
    }

    auto qk1 = [&](const uint32_t* KHb, int kc2, float (&c)[2][4]) {
        #pragma unroll
        for (int nt = 0; nt < 2; nt++)
            c[nt][0] = c[nt][1] = c[nt][2] = c[nt][3] = 0.f;
        #pragma unroll
        for (int kcd = 0; kcd < 4; kcd++) {
            #pragma unroll
            for (int nt = 0; nt < 2; nt++) {
                int base = (kc2 * 2 + nt) * 256 + kcd * 64 + lane * 2;
                uint32_t bh2[2];
                *(uint2*)bh2 = *(const uint2*)&KHb[base];
                mma_bf16(c[nt], AH[kcd], bh2);
            }
        }
    };
    auto qk3 = [&](const uint32_t* KHb, const uint32_t* KLb, int kc2, float (&c)[2][2][4]) {
        #pragma unroll
        for (int nt = 0; nt < 2; nt++)
            #pragma unroll
            for (int s = 0; s < 2; s++)
                c[nt][s][0] = c[nt][s][1] = c[nt][s][2] = c[nt][s][3] = 0.f;
        #pragma unroll
        for (int kcd = 0; kcd < 4; kcd++) {
            #pragma unroll
            for (int nt = 0; nt < 2; nt++) {
                int base = (kc2 * 2 + nt) * 256 + kcd * 64 + lane * 2;
                uint32_t bh2[2], bl2[2];
                *(uint2*)bh2 = *(const uint2*)&KHb[base];
                *(uint2*)bl2 = *(const uint2*)&KLb[base];
                mma_bf16(c[nt][0], AH[kcd], bh2);
                mma_bf16(c[nt][1], AH[kcd], bl2);
                mma_bf16(c[nt][1], AL[kcd], bh2);
            }
        }
    };

    // ================= PASS 1: row sums (1-term QK, compact; validity = pos < N) =================
    float rs0 = 0.f, rs1 = 0.f;
    for (int bt = 0; bt < nt1; bt++) {
        const int cur = bt & 1;
        CP_WAIT0();
        __syncthreads();
        if (bt < nt1 - 1) { pfK1(cur ^ 1, bt + 1); CP_COMMIT(); }

        const uint32_t* KHb = smu + cur * 4096;
        const int pbase = bt * 128;

        #pragma unroll
        for (int kc2 = 0; kc2 < 8; kc2++) {
            float c[2][4];
            qk1(KHb, kc2, c);
            int key0 = pbase + kc2 * 16 + dlo;
            bool v0 = key0 < N, v1 = key0 + 1 < N, v2 = key0 + 8 < N, v3 = key0 + 9 < N;
            rs0 += (v0 ? ex2f(c[0][0] * C_SCALE) : 0.f)
                 + (v1 ? ex2f(c[0][1] * C_SCALE) : 0.f)
                 + (v2 ? ex2f(c[1][0] * C_SCALE) : 0.f)
                 + (v3 ? ex2f(c[1][1] * C_SCALE) : 0.f);
            rs1 += (v0 ? ex2f(c[0][2] * C_SCALE) : 0.f)
                 + (v1 ? ex2f(c[0][3] * C_SCALE) : 0.f)
                 + (v2 ? ex2f(c[1][2] * C_SCALE) : 0.f)
                 + (v3 ? ex2f(c[1][3] * C_SCALE) : 0.f);
        }
    }
    rs0 += __shfl_xor_sync(0xffffffffu, rs0, 1);
    rs0 += __shfl_xor_sync(0xffffffffu, rs0, 2);
    rs1 += __shfl_xor_sync(0xffffffffu, rs1, 1);
    rs1 += __shfl_xor_sync(0xffffffffu, rs1, 2);
    const float li0 = -lg2f(rs0);
    const float li1 = -lg2f(rs1);

    __syncthreads();                       // retire pass-1 buffer reads
    pfK(0, 0); pfV(0, 0); CP_COMMIT();

    float accO[8][4];
    #pragma unroll
    for (int j = 0; j < 8; j++)
        accO[j][0] = accO[j][1] = accO[j][2] = accO[j][3] = 0.f;

    float* wc0 = g_Wc + ((size_t)bh * SQ + qt * MQ + qb + g) * SQ;
    float* wc1 = wc0 + (size_t)8 * SQ;

    // ================= PASS 2: compact Wc write + PV (no predication: V pads are 0) =================
    for (int kt = 0; kt < nt2; kt++) {
        const int cur = kt & 1;
        CP_WAIT0();
        __syncthreads();
        if (kt < nt2 - 1) { pfK(cur ^ 1, kt + 1); pfV(cur ^ 1, kt + 1); CP_COMMIT(); }

        const uint32_t* KHb = smu + U_KH + cur * 2048;
        const uint32_t* KLb = smu + U_KL + cur * 2048;
        const uint32_t* VHb = smu + U_VH + cur * 2048;
        const uint32_t* VLb = smu + U_VL + cur * 2048;
        const size_t ktb = (size_t)kt * 64;

        #pragma unroll
        for (int kc2 = 0; kc2 < 4; kc2++) {
            float c[2][2][4];
            qk3(KHb, KLb, kc2, c);

            float e00 = ex2f(fmaf(c[0][0][0] + c[0][1][0], C_SCALE, li0));
            float e01 = ex2f(fmaf(c[0][0][1] + c[0][1][1], C_SCALE, li0));
            float e02 = ex2f(fmaf(c[0][0][2] + c[0][1][2], C_SCALE, li1));
            float e03 = ex2f(fmaf(c[0][0][3] + c[0][1][3], C_SCALE, li1));
            float e10 = ex2f(fmaf(c[1][0][0] + c[1][1][0], C_SCALE, li0));
            float e11 = ex2f(fmaf(c[1][0][1] + c[1][1][1], C_SCALE, li0));
            float e12 = ex2f(fmaf(c[1][0][2] + c[1][1][2], C_SCALE, li1));
            float e13 = ex2f(fmaf(c[1][0][3] + c[1][1][3], C_SCALE, li1));

            size_t cb = ktb + kc2 * 16 + dlo;
            *(float2*)(wc0 + cb)     = make_float2(e00, e01);
            *(float2*)(wc1 + cb)     = make_float2(e02, e03);
            *(float2*)(wc0 + cb + 8) = make_float2(e10, e11);
            *(float2*)(wc1 + cb + 8) = make_float2(e12, e13);

            uint32_t aWH[4], aWL[4];
            split2(e00, e01, aWH[0], aWL[0]);
            split2(e02, e03, aWH[1], aWL[1]);
            split2(e10, e11, aWH[2], aWL[2]);
            split2(e12, e13, aWH[3], aWL[3]);

            #pragma unroll
            for (int ntd = 0; ntd < 8; ntd++) {
                int base = kc2 * 512 + ntd * 64 + lane * 2;
                uint32_t bh2[2], bl2[2];
                *(uint2*)bh2 = *(const uint2*)&VHb[base];
                *(uint2*)bl2 = *(const uint2*)&VLb[base];
                mma_bf16(accO[ntd], aWH, bh2);
                mma_bf16(accO[ntd], aWL, bh2);
                mma_bf16(accO[ntd], aWH, bl2);
            }
        }
    }

    // ---- output (warp-owned, direct) ----
    {
        float* or0 = Out + ((size_t)bh * SQ + qt * MQ + qb + g) * DDIM + dlo;
        float* or1 = or0 + (size_t)8 * DDIM;
        #pragma unroll
        for (int ntd = 0; ntd < 8; ntd++) {
            *(float2*)(or0 + ntd * 8) = make_float2(accO[ntd][0], accO[ntd][1]);
            *(float2*)(or1 + ntd * 8) = make_float2(accO[ntd][2], accO[ntd][3]);
        }
    }

    // ================= EXPANSION: dense coalesced W from compact Wc =================
    __syncthreads();                       // all pass-2 reads retired; reuse K buffers
    int* s_scan = (int*)(smu + U_KH);      // [2048]
    int* s_mask = (int*)(smu + U_KH + 2048);
    for (int i = t; i < SQ / 4; i += NTH) {
        ((int4*)s_scan)[i] = ((const int4*)&g_scan[b][0])[i];
        ((int4*)s_mask)[i] = ((const int4*)(M + b * SQ))[i];
    }
    __syncthreads();

    const float* wcbase = g_Wc + ((size_t)bh * SQ + (size_t)qt * MQ) * SQ;
    float* wbase = W + ((size_t)bh * SQ + (size_t)qt * MQ) * SQ;
    #pragma unroll 4
    for (int it = 0; it < (MQ * SQ / 4) / NTH; it++) {     // 256 iterations
        int idx4 = it * NTH + t;
        int row = idx4 >> 9;               // 512 float4 per row
        int c4 = idx4 & 511;
        int4 sc = ((const int4*)s_scan)[c4];
        int4 mk = ((const int4*)s_mask)[c4];
        const float* wcrow = wcbase + (size_t)row * SQ;
        float4 v;
        v.x = mk.x ? wcrow[sc.x] : 0.f;
        v.y = mk.y ? wcrow[sc.y] : 0.f;
        v.z = mk.z ? wcrow[sc.z] : 0.f;
        v.w = mk.w ? wcrow[sc.w] : 0.f;
        ((float4*)(wbase + (size_t)row * SQ))[c4] = v;
    }
}

extern "C" void kernel_launch(void* const* d_in, const int* in_sizes, int n_in,
                              void* d_out, int out_size) {
    const float* q = (const float*)d_in[0];
    const float* k = (const float*)d_in[1];
    const float* v = (const float*)d_in[2];
    const int*   m = (const int*)d_in[3];

    float* out = (float*)d_out;
    float* wts = out + (size_t)BB * HH * SQ * DDIM;

    prep_index<<<BB, 1024>>>(m);
    dim3 pgrid(BB * HH * 16, 2);
    prep_split<<<pgrid, 1024>>>(k, v);

    cudaFuncSetAttribute(attn13, cudaFuncAttributeMaxDynamicSharedMemorySize, SMEM_BYTES);
    dim3 grid(SQ / MQ, BB * HH);
    attn13<<<grid, NTH, SMEM_BYTES>>>(q, m, out, wts);
}

// round 14
// speedup vs baseline: 1.1607x; 1.1607x over previous
#include <cuda_runtime.h>
#include <cuda_bf16.h>
#include <cstdint>
#include <math.h>

#define BB 2
#define HH 16
#define SQ 2048
#define DDIM 64
#define MQ 128
#define TKEY 64
#define NTILE (SQ / TKEY)      // 32 (pass 2)
#define NBIG  16               // pass-1 128-key tiles
#define NTH 256
#define C_SCALE 0.18033688011110543f   // 0.125 * log2(e)

// smem layout (u32 units)
#define U_KHL 0                // pass2 KHL [2][4096]; pass1 KH [2][4096] (aliased)
#define U_VHL 8192             // pass2 VHL [2][4096]
#define U_MSK 16384            // [2][128] int
#define SMEM_BYTES (16640 * 4)

// global scratch
__device__ uint32_t g_KH1[32 * 16 * 4096];   // pass-1: hi-only, kcd-paired layout
__device__ uint32_t g_KHL[32 * 16 * 8192];   // pass-2: hi/lo interleaved K
__device__ uint32_t g_VHL[32 * 16 * 8192];   // pass-2: hi/lo interleaved V

static __device__ __forceinline__ uint32_t smem_u32(const void* p) {
    uint32_t a;
    asm("{ .reg .u64 t; cvta.to.shared.u64 t, %1; cvt.u32.u64 %0, t; }" : "=r"(a) : "l"(p));
    return a;
}
static __device__ __forceinline__ void cp16(uint32_t dst, const void* src) {
    asm volatile("cp.async.cg.shared.global [%0], [%1], 16;" :: "r"(dst), "l"(src));
}
#define CP_COMMIT() asm volatile("cp.async.commit_group;" ::: "memory")
#define CP_WAIT0()  asm volatile("cp.async.wait_group 0;" ::: "memory")

static __device__ __forceinline__ float ex2f(float x) {
    float y; asm("ex2.approx.f32 %0, %1;" : "=f"(y) : "f"(x)); return y;
}
static __device__ __forceinline__ float lg2f(float x) {
    float y; asm("lg2.approx.f32 %0, %1;" : "=f"(y) : "f"(x)); return y;
}

static __device__ __forceinline__ void mma_bf16(float* c, const uint32_t* a, const uint32_t* b) {
    asm volatile(
        "mma.sync.aligned.m16n8k16.row.col.f32.bf16.bf16.f32 "
        "{%0,%1,%2,%3}, {%4,%5,%6,%7}, {%8,%9}, {%0,%1,%2,%3};"
        : "+f"(c[0]), "+f"(c[1]), "+f"(c[2]), "+f"(c[3])
        : "r"(a[0]), "r"(a[1]), "r"(a[2]), "r"(a[3]), "r"(b[0]), "r"(b[1]));
}

static __device__ __forceinline__ void split2(float a, float b, uint32_t& hi, uint32_t& lo) {
    __nv_bfloat162 h = __floats2bfloat162_rn(a, b);
    float ra = a - __bfloat162float(__low2bfloat16(h));
    float rb = b - __bfloat162float(__high2bfloat16(h));
    __nv_bfloat162 l = __floats2bfloat162_rn(ra, rb);
    hi = *reinterpret_cast<uint32_t*>(&h);
    lo = *reinterpret_cast<uint32_t*>(&l);
}

// ---------- prep: split K/V once into interleaved frag-native scratch ----------
__global__ __launch_bounds__(1024)
void prep_split(const float* __restrict__ K, const float* __restrict__ V) {
    const int tile = blockIdx.x;               // bh*16 + 128-key tile
    const int t = threadIdx.x;
    const size_t base = (size_t)tile * 128 * DDIM;
    if (blockIdx.y == 0) {
        const float2* src = (const float2*)(K + base);
        uint32_t* d1 = g_KH1 + (size_t)tile * 4096;
        uint32_t* dI = g_KHL + (size_t)tile * 8192;
        #pragma unroll
        for (int i = 0; i < 4; i++) {
            int idx = i * 1024 + t;
            int key = idx >> 5, dp = idx & 31;
            float2 x = src[idx];
            uint32_t hi, lo; split2(x.x, x.y, hi, lo);
            int nt = key >> 3, kcd = dp >> 3;
            int lane = (key & 7) * 4 + (dp & 3);
            int r = (dp >> 2) & 1;
            // pass-1 hi-only, kcd-paired: one LDS.128 covers kcd pair
            d1[((nt * 2 + (kcd >> 1)) * 32 + lane) * 4 + (kcd & 1) * 2 + r] = hi;
            // pass-2 interleaved: [hi0,hi1,lo0,lo1] per (nt,kcd,lane)
            int iq = ((nt * 4 + kcd) * 32 + lane) * 4;
            dI[iq + r] = hi;
            dI[iq + 2 + r] = lo;
        }
    } else {
        const float* src = V + base;
        uint32_t* dI = g_VHL + (size_t)tile * 8192;
        #pragma unroll
        for (int i = 0; i < 4; i++) {
            int idx = i * 1024 + t;
            int d = idx & 63, kp = idx >> 6;
            float va = src[(size_t)(2 * kp) * DDIM + d];
            float vb = src[(size_t)(2 * kp + 1) * DDIM + d];
            uint32_t hi, lo; split2(va, vb, hi, lo);
            int kc2 = kp >> 3, w8 = kp & 7;
            int ntd = d >> 3;
            int lane = (d & 7) * 4 + (w8 & 3);
            int r = w8 >> 2;
            int iq = ((kc2 * 8 + ntd) * 32 + lane) * 4;
            dI[iq + r] = hi;
            dI[iq + 2 + r] = lo;
        }
    }
}

// ---------- main attention kernel: 8 warps, 2 CTAs/SM ----------
__global__ __launch_bounds__(NTH, 2)
void attn14(const float* __restrict__ Q, const int* __restrict__ M,
            float* __restrict__ Out, float* __restrict__ W) {
    extern __shared__ __align__(16) uint32_t smu[];
    const uint32_t sb = smem_u32(smu);

    const int t    = threadIdx.x;
    const int lane = t & 31;
    const int wid  = t >> 5;
    const int g    = lane >> 2;
    const int t4   = lane & 3;
    const int dlo  = 2 * t4;
    const int qb   = wid * 16;

    const int qt = blockIdx.x;
    const int bh = blockIdx.y;
    const int b  = bh / HH;

    const float* qg = Q + ((size_t)bh * SQ + (size_t)qt * MQ) * DDIM;
    const int*   mg = M + b * SQ;

    // ---- pass-1 prefetchers: 128-key tiles, hi-only paired layout ----
    auto pfK1 = [&](int buf, int bt) {
        const uint32_t* s = g_KH1 + ((size_t)bh * 16 + bt) * 4096;
        const uint32_t d = sb + (uint32_t)buf * 4096 * 4;
        #pragma unroll
        for (int c = 0; c < 4; c++) {
            int o = (c * NTH + t) * 4;
            cp16(d + o * 4, s + o);
        }
    };
    auto pfM1 = [&](int buf, int bt) {
        if (t < 32) cp16(sb + (U_MSK + buf * 128 + t * 4) * 4, mg + bt * 128 + t * 4);
    };

    // ---- pass-2 prefetchers: 64-key tiles, interleaved ----
    auto pfK = [&](int buf, int kt64) {
        const size_t off = ((size_t)bh * 16 + (kt64 >> 1)) * 8192 + (size_t)(kt64 & 1) * 4096;
        const uint32_t d = sb + (U_KHL + buf * 4096) * 4;
        #pragma unroll
        for (int c = 0; c < 4; c++) {
            int o = (c * NTH + t) * 4;
            cp16(d + o * 4, g_KHL + off + o);
        }
    };
    auto pfV = [&](int buf, int kt64) {
        const size_t off = ((size_t)bh * 16 + (kt64 >> 1)) * 8192 + (size_t)(kt64 & 1) * 4096;
        const uint32_t d = sb + (U_VHL + buf * 4096) * 4;
        #pragma unroll
        for (int c = 0; c < 4; c++) {
            int o = (c * NTH + t) * 4;
            cp16(d + o * 4, g_VHL + off + o);
        }
    };
    auto pfM = [&](int buf, int kt64) {
        if (t < 16) cp16(sb + (U_MSK + buf * 128 + t * 4) * 4, mg + kt64 * TKEY + t * 4);
    };

    // ---- persistent Q A-fragments (hi/lo) ----
    uint32_t AH[4][4], AL[4][4];
    #pragma unroll
    for (int kc = 0; kc < 4; kc++) {
        const float* r0 = qg + (size_t)(qb + g) * DDIM + kc * 16 + dlo;
        const float* r1 = r0 + 8 * DDIM;
        float2 p0 = *(const float2*)(r0);
        float2 p1 = *(const float2*)(r1);
        float2 p2 = *(const float2*)(r0 + 8);
        float2 p3 = *(const float2*)(r1 + 8);
        split2(p0.x, p0.y, AH[kc][0], AL[kc][0]);
        split2(p1.x, p1.y, AH[kc][1], AL[kc][1]);
        split2(p2.x, p2.y, AH[kc][2], AL[kc][2]);
        split2(p3.x, p3.y, AH[kc][3], AL[kc][3]);
    }

    // pass-1 QK (1-term, kcd-paired LDS.128)
    auto qk1 = [&](const uint32_t* KHb, int kc2, float (&c)[2][4]) {
        #pragma unroll
        for (int nt = 0; nt < 2; nt++)
            c[nt][0] = c[nt][1] = c[nt][2] = c[nt][3] = 0.f;
        #pragma unroll
        for (int nt = 0; nt < 2; nt++) {
            const int ntg = kc2 * 2 + nt;
            #pragma unroll
            for (int p = 0; p < 2; p++) {
                uint32_t q4[4];
                *(uint4*)q4 = *(const uint4*)&KHb[((ntg * 2 + p) * 32 + lane) * 4];
                mma_bf16(c[nt], AH[2 * p],     q4);
                mma_bf16(c[nt], AH[2 * p + 1], q4 + 2);
            }
        }
    };
    // pass-2 QK (3-term, interleaved LDS.128)
    auto qk3 = [&](const uint32_t* KHb, int kc2, float (&c)[2][2][4]) {
        #pragma unroll
        for (int nt = 0; nt < 2; nt++)
            #pragma unroll
            for (int s = 0; s < 2; s++)
                c[nt][s][0] = c[nt][s][1] = c[nt][s][2] = c[nt][s][3] = 0.f;
        #pragma unroll
        for (int kcd = 0; kcd < 4; kcd++) {
            #pragma unroll
            for (int nt = 0; nt < 2; nt++) {
                const int nth = kc2 * 2 + nt;
                uint32_t q4[4];   // [bh0,bh1,bl0,bl1]
                *(uint4*)q4 = *(const uint4*)&KHb[((nth * 4 + kcd) * 32 + lane) * 4];
                mma_bf16(c[nt][0], AH[kcd], q4);
                mma_bf16(c[nt][1], AH[kcd], q4 + 2);
                mma_bf16(c[nt][1], AL[kcd], q4);
            }
        }
    };

    // ================= PASS 1: row sums (1-term QK, 128-key tiles) =================
    pfK1(0, 0); pfM1(0, 0); CP_COMMIT();

    float rs0 = 0.f, rs1 = 0.f;
    for (int bt = 0; bt < NBIG; bt++) {
        const int cur = bt & 1;
        CP_WAIT0();
        __syncthreads();
        if (bt < NBIG - 1) {
            pfK1(cur ^ 1, bt + 1); pfM1(cur ^ 1, bt + 1);
            CP_COMMIT();
        }

        const uint32_t* KHb = smu + cur * 4096;
        const int* mk = (const int*)(smu + U_MSK + cur * 128);

        #pragma unroll
        for (int kc2 = 0; kc2 < 8; kc2++) {
            float c[2][4];
            qk1(KHb, kc2, c);
            int key0 = kc2 * 16 + dlo;
            int m0 = mk[key0], m1 = mk[key0 + 1], m2 = mk[key0 + 8], m3 = mk[key0 + 9];
            rs0 += (m0 ? ex2f(c[0][0] * C_SCALE) : 0.f)
                 + (m1 ? ex2f(c[0][1] * C_SCALE) : 0.f)
                 + (m2 ? ex2f(c[1][0] * C_SCALE) : 0.f)
                 + (m3 ? ex2f(c[1][1] * C_SCALE) : 0.f);
            rs1 += (m0 ? ex2f(c[0][2] * C_SCALE) : 0.f)
                 + (m1 ? ex2f(c[0][3] * C_SCALE) : 0.f)
                 + (m2 ? ex2f(c[1][2] * C_SCALE) : 0.f)
                 + (m3 ? ex2f(c[1][3] * C_SCALE) : 0.f);
        }
    }
    rs0 += __shfl_xor_sync(0xffffffffu, rs0, 1);
    rs0 += __shfl_xor_sync(0xffffffffu, rs0, 2);
    rs1 += __shfl_xor_sync(0xffffffffu, rs1, 1);
    rs1 += __shfl_xor_sync(0xffffffffu, rs1, 2);
    const float li0 = -lg2f(rs0);
    const float li1 = -lg2f(rs1);

    // pass-1 buffers alias pass-2's KHL region: retire pass-1 reads first
    __syncthreads();
    pfK(0, 0); pfV(0, 0); pfM(0, 0); CP_COMMIT();

    float accO[8][4];
    #pragma unroll
    for (int j = 0; j < 8; j++)
        accO[j][0] = accO[j][1] = accO[j][2] = accO[j][3] = 0.f;

    float* wr0 = W + ((size_t)bh * SQ + qt * MQ + qb + g) * SQ;
    float* wr1 = wr0 + (size_t)8 * SQ;

    // ================= PASS 2: W write + PV =================
    for (int kt = 0; kt < NTILE; kt++) {
        const int cur = kt & 1;
        CP_WAIT0();
        __syncthreads();
        if (kt < NTILE - 1) {
            pfK(cur ^ 1, kt + 1); pfV(cur ^ 1, kt + 1); pfM(cur ^ 1, kt + 1);
            CP_COMMIT();
        }

        const uint32_t* KHb = smu + U_KHL + cur * 4096;
        const uint32_t* VHb = smu + U_VHL + cur * 4096;
        const int* mk = (const int*)(smu + U_MSK + cur * 128);
        const size_t ktb = (size_t)kt * TKEY;

        #pragma unroll
        for (int kc2 = 0; kc2 < 4; kc2++) {
            float c[2][2][4];
            qk3(KHb, kc2, c);

            int key0 = kc2 * 16 + dlo;
            int m0 = mk[key0], m1 = mk[key0 + 1], m2 = mk[key0 + 8], m3 = mk[key0 + 9];

            float e00 = m0 ? ex2f(fmaf(c[0][0][0] + c[0][1][0], C_SCALE, li0)) : 0.f;
            float e01 = m1 ? ex2f(fmaf(c[0][0][1] + c[0][1][1], C_SCALE, li0)) : 0.f;
            float e02 = m0 ? ex2f(fmaf(c[0][0][2] + c[0][1][2], C_SCALE, li1)) : 0.f;
            float e03 = m1 ? ex2f(fmaf(c[0][0][3] + c[0][1][3], C_SCALE, li1)) : 0.f;
            float e10 = m2 ? ex2f(fmaf(c[1][0][0] + c[1][1][0], C_SCALE, li0)) : 0.f;
            float e11 = m3 ? ex2f(fmaf(c[1][0][1] + c[1][1][1], C_SCALE, li0)) : 0.f;
            float e12 = m2 ? ex2f(fmaf(c[1][0][2] + c[1][1][2], C_SCALE, li1)) : 0.f;
            float e13 = m3 ? ex2f(fmaf(c[1][0][3] + c[1][1][3], C_SCALE, li1)) : 0.f;

            size_t cb = ktb + key0;
            *(float2*)(wr0 + cb)     = make_float2(e00, e01);
            *(float2*)(wr1 + cb)     = make_float2(e02, e03);
            *(float2*)(wr0 + cb + 8) = make_float2(e10, e11);
            *(float2*)(wr1 + cb + 8) = make_float2(e12, e13);

            uint32_t aWH[4], aWL[4];
            split2(e00, e01, aWH[0], aWL[0]);
            split2(e02, e03, aWH[1], aWL[1]);
            split2(e10, e11, aWH[2], aWL[2]);
            split2(e12, e13, aWH[3], aWL[3]);

            #pragma unroll
            for (int ntd = 0; ntd < 8; ntd++) {
                uint32_t v4[4];   // [bh0,bh1,bl0,bl1]
                *(uint4*)v4 = *(const uint4*)&VHb[((kc2 * 8 + ntd) * 32 + lane) * 4];
                mma_bf16(accO[ntd], aWH, v4);
                mma_bf16(accO[ntd], aWL, v4);
                mma_bf16(accO[ntd], aWH, v4 + 2);
            }
        }
    }

    // ---- output (warp-owned, direct) ----
    float* or0 = Out + ((size_t)bh * SQ + qt * MQ + qb + g) * DDIM + dlo;
    float* or1 = or0 + (size_t)8 * DDIM;
    #pragma unroll
    for (int ntd = 0; ntd < 8; ntd++) {
        *(float2*)(or0 + ntd * 8) = make_float2(accO[ntd][0], accO[ntd][1]);
        *(float2*)(or1 + ntd * 8) = make_float2(accO[ntd][2], accO[ntd][3]);
    }
}

extern "C" void kernel_launch(void* const* d_in, const int* in_sizes, int n_in,
                              void* d_out, int out_size) {
    const float* q = (const float*)d_in[0];
    const float* k = (const float*)d_in[1];
    const float* v = (const float*)d_in[2];
    const int*   m = (const int*)d_in[3];

    float* out = (float*)d_out;
    float* wts = out + (size_t)BB * HH * SQ * DDIM;

    dim3 pgrid(BB * HH * 16, 2);
    prep_split<<<pgrid, 1024>>>(k, v);

    cudaFuncSetAttribute(attn14, cudaFuncAttributeMaxDynamicSharedMemorySize, SMEM_BYTES);
    dim3 grid(SQ / MQ, BB * HH);
    attn14<<<grid, NTH, SMEM_BYTES>>>(q, m, out, wts);
}

// round 15
// speedup vs baseline: 1.2810x; 1.1036x over previous
#include <cuda_runtime.h>
#include <cuda_bf16.h>
#include <cstdint>
#include <math.h>

#define BB 2
#define HH 16
#define SQ 2048
#define DDIM 64
#define MQ 128
#define TKEY 64
#define NTILE (SQ / TKEY)      // 32 (pass 2)
#define NTH 256
#define C_SCALE 0.18033688011110543f   // 0.125 * log2(e)
#define NEGB (-1250.0f)

// smem layout (u32 units)
#define U_KHL 0                // pass2 KHL [2][4096]; pass1 K1C [2][4096] (aliased)
#define U_VHL 8192             // pass2 VHL [2][4096]
#define U_BIA 16384            // [2][64] float (pass-2 bias)
#define SMEM_BYTES (16640 * 4)

// global scratch
__device__ uint32_t g_K1C[32 * 16 * 4096];   // pass-1: COMPACTED hi-only, kcd-paired
__device__ uint32_t g_KHL[32 * 16 * 8192];   // pass-2: hi/lo interleaved K (dense)
__device__ uint32_t g_VHL[32 * 16 * 8192];   // pass-2: hi/lo interleaved V (dense)
__device__ int   g_idx[BB][SQ];
__device__ int   g_N[BB];
__device__ float g_bias[BB][SQ];

static __device__ __forceinline__ uint32_t smem_u32(const void* p) {
    uint32_t a;
    asm("{ .reg .u64 t; cvta.to.shared.u64 t, %1; cvt.u32.u64 %0, t; }" : "=r"(a) : "l"(p));
    return a;
}
static __device__ __forceinline__ void cp16(uint32_t dst, const void* src) {
    asm volatile("cp.async.cg.shared.global [%0], [%1], 16;" :: "r"(dst), "l"(src));
}
#define CP_COMMIT() asm volatile("cp.async.commit_group;" ::: "memory")
#define CP_WAIT0()  asm volatile("cp.async.wait_group 0;" ::: "memory")

static __device__ __forceinline__ float ex2f(float x) {
    float y; asm("ex2.approx.f32 %0, %1;" : "=f"(y) : "f"(x)); return y;
}
static __device__ __forceinline__ float lg2f(float x) {
    float y; asm("lg2.approx.f32 %0, %1;" : "=f"(y) : "f"(x)); return y;
}

static __device__ __forceinline__ void mma_bf16(float* c, const uint32_t* a, const uint32_t* b) {
    asm volatile(
        "mma.sync.aligned.m16n8k16.row.col.f32.bf16.bf16.f32 "
        "{%0,%1,%2,%3}, {%4,%5,%6,%7}, {%8,%9}, {%0,%1,%2,%3};"
        : "+f"(c[0]), "+f"(c[1]), "+f"(c[2]), "+f"(c[3])
        : "r"(a[0]), "r"(a[1]), "r"(a[2]), "r"(a[3]), "r"(b[0]), "r"(b[1]));
}

static __device__ __forceinline__ void split2(float a, float b, uint32_t& hi, uint32_t& lo) {
    __nv_bfloat162 h = __floats2bfloat162_rn(a, b);
    float ra = a - __bfloat162float(__low2bfloat16(h));
    float rb = b - __bfloat162float(__high2bfloat16(h));
    __nv_bfloat162 l = __floats2bfloat162_rn(ra, rb);
    hi = *reinterpret_cast<uint32_t*>(&h);
    lo = *reinterpret_cast<uint32_t*>(&l);
}

// ---------- prep A: compacted index + bias + count per batch ----------
__global__ __launch_bounds__(1024)
void prep_index(const int* __restrict__ M) {
    const int b = blockIdx.x;
    const int t = threadIdx.x;
    __shared__ int a[1024];
    int m0 = M[b * SQ + 2 * t];
    int m1 = M[b * SQ + 2 * t + 1];
    g_bias[b][2 * t]     = m0 ? 0.f : NEGB;
    g_bias[b][2 * t + 1] = m1 ? 0.f : NEGB;
    a[t] = m0 + m1;
    __syncthreads();
    for (int off = 1; off < 1024; off <<= 1) {
        int v = a[t];
        if (t >= off) v += a[t - off];
        __syncthreads();
        a[t] = v;
        __syncthreads();
    }
    int total = a[1023];
    int excl = a[t] - (m0 + m1);
    if (m0) g_idx[b][excl] = 2 * t;
    if (m1) g_idx[b][excl + m0] = 2 * t + 1;
    for (int i = t; i < SQ; i += 1024)
        if (i >= total) g_idx[b][i] = -1;
    if (t == 0) g_N[b] = total;
}

// ---------- prep B: compacted hi-only K scratch for pass 1 ----------
__global__ __launch_bounds__(1024)
void prep_splitC(const float* __restrict__ K) {
    const int tile = blockIdx.x;               // bh*16 + compact 128-key tile
    const int bh = tile >> 4;
    const int b  = bh / HH;
    const int tloc = tile & 15;
    const int t = threadIdx.x;
    uint32_t* d1 = g_K1C + (size_t)tile * 4096;
    #pragma unroll
    for (int i = 0; i < 4; i++) {
        int idx = i * 1024 + t;
        int key = idx >> 5, dp = idx & 31;
        int orig = g_idx[b][tloc * 128 + key];
        float2 x = make_float2(0.f, 0.f);
        if (orig >= 0)
            x = ((const float2*)(K + ((size_t)bh * SQ + orig) * DDIM))[dp];
        __nv_bfloat162 h = __floats2bfloat162_rn(x.x, x.y);
        int nt = key >> 3, kcd = dp >> 3;
        int lane = (key & 7) * 4 + (dp & 3);
        int r = (dp >> 2) & 1;
        d1[((nt * 2 + (kcd >> 1)) * 32 + lane) * 4 + (kcd & 1) * 2 + r] =
            *reinterpret_cast<uint32_t*>(&h);
    }
}

// ---------- prep C: dense interleaved hi/lo K,V scratch for pass 2 ----------
__global__ __launch_bounds__(1024)
void prep_split(const float* __restrict__ K, const float* __restrict__ V) {
    const int tile = blockIdx.x;
    const int t = threadIdx.x;
    const size_t base = (size_t)tile * 128 * DDIM;
    if (blockIdx.y == 0) {
        const float2* src = (const float2*)(K + base);
        uint32_t* dI = g_KHL + (size_t)tile * 8192;
        #pragma unroll
        for (int i = 0; i < 4; i++) {
            int idx = i * 1024 + t;
            int key = idx >> 5, dp = idx & 31;
            float2 x = src[idx];
            uint32_t hi, lo; split2(x.x, x.y, hi, lo);
            int nt = key >> 3, kcd = dp >> 3;
            int lane = (key & 7) * 4 + (dp & 3);
            int r = (dp >> 2) & 1;
            int iq = ((nt * 4 + kcd) * 32 + lane) * 4;
            dI[iq + r] = hi;
            dI[iq + 2 + r] = lo;
        }
    } else {
        const float* src = V + base;
        uint32_t* dI = g_VHL + (size_t)tile * 8192;
        #pragma unroll
        for (int i = 0; i < 4; i++) {
            int idx = i * 1024 + t;
            int d = idx & 63, kp = idx >> 6;
            float va = src[(size_t)(2 * kp) * DDIM + d];
            float vb = src[(size_t)(2 * kp + 1) * DDIM + d];
            uint32_t hi, lo; split2(va, vb, hi, lo);
            int kc2 = kp >> 3, w8 = kp & 7;
            int ntd = d >> 3;
            int lane = (d & 7) * 4 + (w8 & 3);
            int r = w8 >> 2;
            int iq = ((kc2 * 8 + ntd) * 32 + lane) * 4;
            dI[iq + r] = hi;
            dI[iq + 2 + r] = lo;
        }
    }
}

// ---------- main attention kernel: 8 warps, 2 CTAs/SM ----------
__global__ __launch_bounds__(NTH, 2)
void attn15(const float* __restrict__ Q,
            float* __restrict__ Out, float* __restrict__ W) {
    extern __shared__ __align__(16) uint32_t smu[];
    const uint32_t sb = smem_u32(smu);

    const int t    = threadIdx.x;
    const int lane = t & 31;
    const int wid  = t >> 5;
    const int g    = lane >> 2;
    const int t4   = lane & 3;
    const int dlo  = 2 * t4;
    const int qb   = wid * 16;

    const int qt = blockIdx.x;
    const int bh = blockIdx.y;
    const int b  = bh / HH;

    const float* qg = Q + ((size_t)bh * SQ + (size_t)qt * MQ) * DDIM;
    const int N = g_N[b];
    const int nt1 = (N + 127) >> 7;            // compacted pass-1 tiles

    // ---- pass-1 prefetcher: compacted 128-key tiles, hi-only paired layout ----
    auto pfK1 = [&](int buf, int bt) {
        const uint32_t* s = g_K1C + ((size_t)bh * 16 + bt) * 4096;
        const uint32_t d = sb + (uint32_t)buf * 4096 * 4;
        #pragma unroll
        for (int c = 0; c < 4; c++) {
            int o = (c * NTH + t) * 4;
            cp16(d + o * 4, s + o);
        }
    };
    // ---- pass-2 prefetchers: dense 64-key tiles, interleaved ----
    auto pfK = [&](int buf, int kt64) {
        const size_t off = ((size_t)bh * 16 + (kt64 >> 1)) * 8192 + (size_t)(kt64 & 1) * 4096;
        const uint32_t d = sb + (U_KHL + buf * 4096) * 4;
        #pragma unroll
        for (int c = 0; c < 4; c++) {
            int o = (c * NTH + t) * 4;
            cp16(d + o * 4, g_KHL + off + o);
        }
    };
    auto pfV = [&](int buf, int kt64) {
        const size_t off = ((size_t)bh * 16 + (kt64 >> 1)) * 8192 + (size_t)(kt64 & 1) * 4096;
        const uint32_t d = sb + (U_VHL + buf * 4096) * 4;
        #pragma unroll
        for (int c = 0; c < 4; c++) {
            int o = (c * NTH + t) * 4;
            cp16(d + o * 4, g_VHL + off + o);
        }
    };
    auto pfB = [&](int buf, int kt64) {
        if (t < 16) cp16(sb + (U_BIA + buf * 64 + t * 4) * 4, &g_bias[b][kt64 * TKEY + t * 4]);
    };

    pfK1(0, 0); CP_COMMIT();

    // ---- persistent Q A-fragments (hi/lo) ----
    uint32_t AH[4][4], AL[4][4];
    #pragma unroll
    for (int kc = 0; kc < 4; kc++) {
        const float* r0 = qg + (size_t)(qb + g) * DDIM + kc * 16 + dlo;
        const float* r1 = r0 + 8 * DDIM;
        float2 p0 = *(const float2*)(r0);
        float2 p1 = *(const float2*)(r1);
        float2 p2 = *(const float2*)(r0 + 8);
        float2 p3 = *(const float2*)(r1 + 8);
        split2(p0.x, p0.y, AH[kc][0], AL[kc][0]);
        split2(p1.x, p1.y, AH[kc][1], AL[kc][1]);
        split2(p2.x, p2.y, AH[kc][2], AL[kc][2]);
        split2(p3.x, p3.y, AH[kc][3], AL[kc][3]);
    }

    // pass-1 QK (1-term, kcd-paired LDS.128)
    auto qk1 = [&](const uint32_t* KHb, int kc2, float (&c)[2][4]) {
        #pragma unroll
        for (int nt = 0; nt < 2; nt++)
            c[nt][0] = c[nt][1] = c[nt][2] = c[nt][3] = 0.f;
        #pragma unroll
        for (int nt = 0; nt < 2; nt++) {
            const int ntg = kc2 * 2 + nt;
            #pragma unroll
            for (int p = 0; p < 2; p++) {
                uint32_t q4[4];
                *(uint4*)q4 = *(const uint4*)&KHb[((ntg * 2 + p) * 32 + lane) * 4];
                mma_bf16(c[nt], AH[2 * p],     q4);
                mma_bf16(c[nt], AH[2 * p + 1], q4 + 2);
            }
        }
    };
    // pass-2 QK (3-term, interleaved LDS.128)
    auto qk3 = [&](const uint32_t* KHb, int kc2, float (&c)[2][2][4]) {
        #pragma unroll
        for (int nt = 0; nt < 2; nt++)
            #pragma unroll
            for (int s = 0; s < 2; s++)
                c[nt][s][0] = c[nt][s][1] = c[nt][s][2] = c[nt][s][3] = 0.f;
        #pragma unroll
        for (int kcd = 0; kcd < 4; kcd++) {
            #pragma unroll
            for (int nt = 0; nt < 2; nt++) {
                const int nth = kc2 * 2 + nt;
                uint32_t q4[4];   // [bh0,bh1,bl0,bl1]
                *(uint4*)q4 = *(const uint4*)&KHb[((nth * 4 + kcd) * 32 + lane) * 4];
                mma_bf16(c[nt][0], AH[kcd], q4);
                mma_bf16(c[nt][1], AH[kcd], q4 + 2);
                mma_bf16(c[nt][1], AL[kcd], q4);
            }
        }
    };

    // ================= PASS 1: row sums (1-term QK, compacted keys, no masks) =================
    float rs0 = 0.f, rs1 = 0.f;
    for (int bt = 0; bt < nt1; bt++) {
        const int cur = bt & 1;
        CP_WAIT0();
        __syncthreads();
        if (bt < nt1 - 1) { pfK1(cur ^ 1, bt + 1); CP_COMMIT(); }

        const uint32_t* KHb = smu + cur * 4096;

        #pragma unroll
        for (int kc2 = 0; kc2 < 8; kc2++) {
            float c[2][4];
            qk1(KHb, kc2, c);
            rs0 += ex2f(c[0][0] * C_SCALE) + ex2f(c[0][1] * C_SCALE)
                 + ex2f(c[1][0] * C_SCALE) + ex2f(c[1][1] * C_SCALE);
            rs1 += ex2f(c[0][2] * C_SCALE) + ex2f(c[0][3] * C_SCALE)
                 + ex2f(c[1][2] * C_SCALE) + ex2f(c[1][3] * C_SCALE);
        }
    }
    // pad correction: each zero-padded column contributed exp2(0)=1
    {
        int cnt = 0;
        const int lastb = (nt1 - 1) * 128;
        #pragma unroll
        for (int kc2 = 0; kc2 < 8; kc2++) {
            int p = lastb + kc2 * 16 + dlo;
            cnt += (p >= N) + (p + 1 >= N) + (p + 8 >= N) + (p + 9 >= N);
        }
        rs0 -= (float)cnt;
        rs1 -= (float)cnt;
    }
    rs0 += __shfl_xor_sync(0xffffffffu, rs0, 1);
    rs0 += __shfl_xor_sync(0xffffffffu, rs0, 2);
    rs1 += __shfl_xor_sync(0xffffffffu, rs1, 1);
    rs1 += __shfl_xor_sync(0xffffffffu, rs1, 2);
    const float li0 = -lg2f(rs0);
    const float li1 = -lg2f(rs1);

    // pass-1 buffers alias pass-2's KHL region: retire pass-1 reads first
    __syncthreads();
    pfK(0, 0); pfV(0, 0); pfB(0, 0); CP_COMMIT();

    float accO[8][4];
    #pragma unroll
    for (int j = 0; j < 8; j++)
        accO[j][0] = accO[j][1] = accO[j][2] = accO[j][3] = 0.f;

    float* wr0 = W + ((size_t)bh * SQ + qt * MQ + qb + g) * SQ;
    float* wr1 = wr0 + (size_t)8 * SQ;

    // ================= PASS 2: W write + PV (dense, bias-folded mask) =================
    for (int kt = 0; kt < NTILE; kt++) {
        const int cur = kt & 1;
        CP_WAIT0();
        __syncthreads();
        if (kt < NTILE - 1) {
            pfK(cur ^ 1, kt + 1); pfV(cur ^ 1, kt + 1); pfB(cur ^ 1, kt + 1);
            CP_COMMIT();
        }

        const uint32_t* KHb = smu + U_KHL + cur * 4096;
        const uint32_t* VHb = smu + U_VHL + cur * 4096;
        const float* bbp = (const float*)(smu + U_BIA + cur * 64);
        const size_t ktb = (size_t)kt * TKEY;

        #pragma unroll
        for (int kc2 = 0; kc2 < 4; kc2++) {
            float c[2][2][4];
            qk3(KHb, kc2, c);

            int key0 = kc2 * 16 + dlo;
            float b0 = bbp[key0], b1 = bbp[key0 + 1], b2 = bbp[key0 + 8], b3 = bbp[key0 + 9];

            float e00 = ex2f(fmaf(c[0][0][0] + c[0][1][0], C_SCALE, li0 + b0));
            float e01 = ex2f(fmaf(c[0][0][1] + c[0][1][1], C_SCALE, li0 + b1));
            float e02 = ex2f(fmaf(c[0][0][2] + c[0][1][2], C_SCALE, li1 + b0));
            float e03 = ex2f(fmaf(c[0][0][3] + c[0][1][3], C_SCALE, li1 + b1));
            float e10 = ex2f(fmaf(c[1][0][0] + c[1][1][0], C_SCALE, li0 + b2));
            float e11 = ex2f(fmaf(c[1][0][1] + c[1][1][1], C_SCALE, li0 + b3));
            float e12 = ex2f(fmaf(c[1][0][2] + c[1][1][2], C_SCALE, li1 + b2));
            float e13 = ex2f(fmaf(c[1][0][3] + c[1][1][3], C_SCALE, li1 + b3));

            uint32_t aWH[4], aWL[4];
            split2(e00, e01, aWH[0], aWL[0]);
            split2(e02, e03, aWH[1], aWL[1]);
            split2(e10, e11, aWH[2], aWL[2]);
            split2(e12, e13, aWH[3], aWL[3]);

            #pragma unroll
            for (int ntd = 0; ntd < 8; ntd++) {
                uint32_t v4[4];   // [bh0,bh1,bl0,bl1]
                *(uint4*)v4 = *(const uint4*)&VHb[((kc2 * 8 + ntd) * 32 + lane) * 4];
                mma_bf16(accO[ntd], aWH, v4);
                mma_bf16(accO[ntd], aWL, v4);
                mma_bf16(accO[ntd], aWH, v4 + 2);
            }

            size_t cb = ktb + key0;
            *(float2*)(wr0 + cb)     = make_float2(e00, e01);
            *(float2*)(wr1 + cb)     = make_float2(e02, e03);
            *(float2*)(wr0 + cb + 8) = make_float2(e10, e11);
            *(float2*)(wr1 + cb + 8) = make_float2(e12, e13);
        }
    }

    // ---- output (warp-owned, direct) ----
    float* or0 = Out + ((size_t)bh * SQ + qt * MQ + qb + g) * DDIM + dlo;
    float* or1 = or0 + (size_t)8 * DDIM;
    #pragma unroll
    for (int ntd = 0; ntd < 8; ntd++) {
        *(float2*)(or0 + ntd * 8) = make_float2(accO[ntd][0], accO[ntd][1]);
        *(float2*)(or1 + ntd * 8) = make_float2(accO[ntd][2], accO[ntd][3]);
    }
}

extern "C" void kernel_launch(void* const* d_in, const int* in_sizes, int n_in,
                              void* d_out, int out_size) {
    const float* q = (const float*)d_in[0];
    const float* k = (const float*)d_in[1];
    const float* v = (const float*)d_in[2];
    const int*   m = (const int*)d_in[3];

    float* out = (float*)d_out;
    float* wts = out + (size_t)BB * HH * SQ * DDIM;

    prep_index<<<BB, 1024>>>(m);
    prep_splitC<<<BB * HH * 16, 1024>>>(k);
    dim3 pgrid(BB * HH * 16, 2);
    prep_split<<<pgrid, 1024>>>(k, v);

    cudaFuncSetAttribute(attn15, cudaFuncAttributeMaxDynamicSharedMemorySize, SMEM_BYTES);
    dim3 grid(SQ / MQ, BB * HH);
    attn15<<<grid, NTH, SMEM_BYTES>>>(q, out, wts);
}

// round 16
// speedup vs baseline: 1.2949x; 1.0109x over previous
#include <cuda_runtime.h>
#include <cuda_bf16.h>
#include <cstdint>
#include <math.h>

#define BB 2
#define HH 16
#define SQ 2048
#define DDIM 64
#define MQ 128
#define TKEY 64
#define NTILE (SQ / TKEY)      // 32 (pass 2)
#define NTH 256
#define C_SCALE 0.18033688011110543f   // 0.125 * log2(e)
#define NEGB (-1250.0f)

// smem layout (u32 units)
#define U_KHL 0                // pass2 KHL [2][4096]; pass1 K1C [2][8192] spans KHL+VHL
#define U_VHL 8192             // pass2 VHL [2][4096]
#define U_BIA 16384            // [2][64] float (pass-2 bias)
#define SMEM_BYTES (16640 * 4)

// global scratch
__device__ uint32_t g_K1C[32 * 16 * 4096];   // pass-1: COMPACTED hi-only, kcd-paired
__device__ uint32_t g_KHL[32 * 16 * 8192];   // pass-2: hi/lo interleaved K (dense)
__device__ uint32_t g_VHL[32 * 16 * 8192];   // pass-2: hi/lo interleaved V (dense)
__device__ int   g_idx[BB][SQ];
__device__ int   g_N[BB];
__device__ float g_bias[BB][SQ];

static __device__ __forceinline__ uint32_t smem_u32(const void* p) {
    uint32_t a;
    asm("{ .reg .u64 t; cvta.to.shared.u64 t, %1; cvt.u32.u64 %0, t; }" : "=r"(a) : "l"(p));
    return a;
}
static __device__ __forceinline__ void cp16(uint32_t dst, const void* src) {
    asm volatile("cp.async.cg.shared.global [%0], [%1], 16;" :: "r"(dst), "l"(src));
}
#define CP_COMMIT() asm volatile("cp.async.commit_group;" ::: "memory")
#define CP_WAIT0()  asm volatile("cp.async.wait_group 0;" ::: "memory")

static __device__ __forceinline__ float ex2f(float x) {
    float y; asm("ex2.approx.f32 %0, %1;" : "=f"(y) : "f"(x)); return y;
}
static __device__ __forceinline__ float lg2f(float x) {
    float y; asm("lg2.approx.f32 %0, %1;" : "=f"(y) : "f"(x)); return y;
}
static __device__ __forceinline__ void stg_cs2(float* p, float a, float b) {
    asm volatile("st.global.cs.v2.f32 [%0], {%1, %2};" :: "l"(p), "f"(a), "f"(b) : "memory");
}

static __device__ __forceinline__ void mma_bf16(float* c, const uint32_t* a, const uint32_t* b) {
    asm volatile(
        "mma.sync.aligned.m16n8k16.row.col.f32.bf16.bf16.f32 "
        "{%0,%1,%2,%3}, {%4,%5,%6,%7}, {%8,%9}, {%0,%1,%2,%3};"
        : "+f"(c[0]), "+f"(c[1]), "+f"(c[2]), "+f"(c[3])
        : "r"(a[0]), "r"(a[1]), "r"(a[2]), "r"(a[3]), "r"(b[0]), "r"(b[1]));
}

static __device__ __forceinline__ void split2(float a, float b, uint32_t& hi, uint32_t& lo) {
    __nv_bfloat162 h = __floats2bfloat162_rn(a, b);
    float ra = a - __bfloat162float(__low2bfloat16(h));
    float rb = b - __bfloat162float(__high2bfloat16(h));
    __nv_bfloat162 l = __floats2bfloat162_rn(ra, rb);
    hi = *reinterpret_cast<uint32_t*>(&h);
    lo = *reinterpret_cast<uint32_t*>(&l);
}

// ---------- prep A: compacted index + bias + count per batch ----------
__global__ __launch_bounds__(1024)
void prep_index(const int* __restrict__ M) {
    const int b = blockIdx.x;
    const int t = threadIdx.x;
    __shared__ int a[1024];
    int m0 = M[b * SQ + 2 * t];
    int m1 = M[b * SQ + 2 * t + 1];
    g_bias[b][2 * t]     = m0 ? 0.f : NEGB;
    g_bias[b][2 * t + 1] = m1 ? 0.f : NEGB;
    a[t] = m0 + m1;
    __syncthreads();
    for (int off = 1; off < 1024; off <<= 1) {
        int v = a[t];
        if (t >= off) v += a[t - off];
        __syncthreads();
        a[t] = v;
        __syncthreads();
    }
    int total = a[1023];
    int excl = a[t] - (m0 + m1);
    if (m0) g_idx[b][excl] = 2 * t;
    if (m1) g_idx[b][excl + m0] = 2 * t + 1;
    for (int i = t; i < SQ; i += 1024)
        if (i >= total) g_idx[b][i] = -1;
    if (t == 0) g_N[b] = total;
}

// ---------- prep B (fused): dense K, dense V, compacted K ----------
__global__ __launch_bounds__(1024)
void prep_split(const float* __restrict__ K, const float* __restrict__ V) {
    const int tile = blockIdx.x;               // bh*16 + 128-key tile
    const int t = threadIdx.x;
    const size_t base = (size_t)tile * 128 * DDIM;
    if (blockIdx.y == 0) {
        const float2* src = (const float2*)(K + base);
        uint32_t* dI = g_KHL + (size_t)tile * 8192;
        #pragma unroll
        for (int i = 0; i < 4; i++) {
            int idx = i * 1024 + t;
            int key = idx >> 5, dp = idx & 31;
            float2 x = src[idx];
            uint32_t hi, lo; split2(x.x, x.y, hi, lo);
            int nt = key >> 3, kcd = dp >> 3;
            int lane = (key & 7) * 4 + (dp & 3);
            int r = (dp >> 2) & 1;
            int iq = ((nt * 4 + kcd) * 32 + lane) * 4;
            dI[iq + r] = hi;
            dI[iq + 2 + r] = lo;
        }
    } else if (blockIdx.y == 1) {
        const float* src = V + base;
        uint32_t* dI = g_VHL + (size_t)tile * 8192;
        #pragma unroll
        for (int i = 0; i < 4; i++) {
            int idx = i * 1024 + t;
            int d = idx & 63, kp = idx >> 6;
            float va = src[(size_t)(2 * kp) * DDIM + d];
            float vb = src[(size_t)(2 * kp + 1) * DDIM + d];
            uint32_t hi, lo; split2(va, vb, hi, lo);
            int kc2 = kp >> 3, w8 = kp & 7;
            int ntd = d >> 3;
            int lane = (d & 7) * 4 + (w8 & 3);
            int r = w8 >> 2;
            int iq = ((kc2 * 8 + ntd) * 32 + lane) * 4;
            dI[iq + r] = hi;
            dI[iq + 2 + r] = lo;
        }
    } else {
        // compacted hi-only K for pass 1
        const int bh = tile >> 4;
        const int b  = bh / HH;
        const int tloc = tile & 15;
        uint32_t* d1 = g_K1C + (size_t)tile * 4096;
        #pragma unroll
        for (int i = 0; i < 4; i++) {
            int idx = i * 1024 + t;
            int key = idx >> 5, dp = idx & 31;
            int orig = g_idx[b][tloc * 128 + key];
            float2 x = make_float2(0.f, 0.f);
            if (orig >= 0)
                x = ((const float2*)(K + ((size_t)bh * SQ + orig) * DDIM))[dp];
            __nv_bfloat162 h = __floats2bfloat162_rn(x.x, x.y);
            int nt = key >> 3, kcd = dp >> 3;
            int lane = (key & 7) * 4 + (dp & 3);
            int r = (dp >> 2) & 1;
            d1[((nt * 2 + (kcd >> 1)) * 32 + lane) * 4 + (kcd & 1) * 2 + r] =
                *reinterpret_cast<uint32_t*>(&h);
        }
    }
}

// ---------- main attention kernel: 8 warps, 2 CTAs/SM ----------
__global__ __launch_bounds__(NTH, 2)
void attn16(const float* __restrict__ Q,
            float* __restrict__ Out, float* __restrict__ W) {
    extern __shared__ __align__(16) uint32_t smu[];
    const uint32_t sb = smem_u32(smu);

    const int t    = threadIdx.x;
    const int lane = t & 31;
    const int wid  = t >> 5;
    const int g    = lane >> 2;
    const int t4   = lane & 3;
    const int dlo  = 2 * t4;
    const int qb   = wid * 16;

    const int qt = blockIdx.x;
    const int bh = blockIdx.y;
    const int b  = bh / HH;

    const float* qg = Q + ((size_t)bh * SQ + (size_t)qt * MQ) * DDIM;
    const int N = g_N[b];
    const int nt1 = (N + 255) >> 8;            // compacted pass-1 256-key tiles

    // ---- pass-1 prefetcher: compacted 256-key tiles (two contiguous K1C blocks) ----
    auto pfK1 = [&](int buf, int bt) {
        const uint32_t* s = g_K1C + ((size_t)bh * 16 + bt * 2) * 4096;
        const uint32_t d = sb + (uint32_t)buf * 8192 * 4;
        #pragma unroll
        for (int c = 0; c < 8; c++) {
            int o = (c * NTH + t) * 4;
            cp16(d + o * 4, s + o);
        }
    };
    // ---- pass-2 prefetchers: dense 64-key tiles, interleaved ----
    auto pfK = [&](int buf, int kt64) {
        const size_t off = ((size_t)bh * 16 + (kt64 >> 1)) * 8192 + (size_t)(kt64 & 1) * 4096;
        const uint32_t d = sb + (U_KHL + buf * 4096) * 4;
        #pragma unroll
        for (int c = 0; c < 4; c++) {
            int o = (c * NTH + t) * 4;
            cp16(d + o * 4, g_KHL + off + o);
        }
    };
    auto pfV = [&](int buf, int kt64) {
        const size_t off = ((size_t)bh * 16 + (kt64 >> 1)) * 8192 + (size_t)(kt64 & 1) * 4096;
        const uint32_t d = sb + (U_VHL + buf * 4096) * 4;
        #pragma unroll
        for (int c = 0; c < 4; c++) {
            int o = (c * NTH + t) * 4;
            cp16(d + o * 4, g_VHL + off + o);
        }
    };
    auto pfB = [&](int buf, int kt64) {
        if (t < 16) cp16(sb + (U_BIA + buf * 64 + t * 4) * 4, &g_bias[b][kt64 * TKEY + t * 4]);
    };

    pfK1(0, 0); CP_COMMIT();

    // ---- persistent Q A-fragments (hi/lo) ----
    uint32_t AH[4][4], AL[4][4];
    #pragma unroll
    for (int kc = 0; kc < 4; kc++) {
        const float* r0 = qg + (size_t)(qb + g) * DDIM + kc * 16 + dlo;
        const float* r1 = r0 + 8 * DDIM;
        float2 p0 = *(const float2*)(r0);
        float2 p1 = *(const float2*)(r1);
        float2 p2 = *(const float2*)(r0 + 8);
        float2 p3 = *(const float2*)(r1 + 8);
        split2(p0.x, p0.y, AH[kc][0], AL[kc][0]);
        split2(p1.x, p1.y, AH[kc][1], AL[kc][1]);
        split2(p2.x, p2.y, AH[kc][2], AL[kc][2]);
        split2(p3.x, p3.y, AH[kc][3], AL[kc][3]);
    }

    // pass-1 QK (1-term, kcd-paired LDS.128, 256-key tile addressing)
    auto qk1 = [&](const uint32_t* KHb, int kc2, float (&c)[2][4]) {
        #pragma unroll
        for (int nt = 0; nt < 2; nt++)
            c[nt][0] = c[nt][1] = c[nt][2] = c[nt][3] = 0.f;
        #pragma unroll
        for (int nt = 0; nt < 2; nt++) {
            const int ntg = kc2 * 2 + nt;
            const int blk = (ntg >> 4) * 4096;
            const int ntl = ntg & 15;
            #pragma unroll
            for (int p = 0; p < 2; p++) {
                uint32_t q4[4];
                *(uint4*)q4 = *(const uint4*)&KHb[blk + ((ntl * 2 + p) * 32 + lane) * 4];
                mma_bf16(c[nt], AH[2 * p],     q4);
                mma_bf16(c[nt], AH[2 * p + 1], q4 + 2);
            }
        }
    };
    // pass-2 QK (3-term, interleaved LDS.128)
    auto qk3 = [&](const uint32_t* KHb, int kc2, float (&c)[2][2][4]) {
        #pragma unroll
        for (int nt = 0; nt < 2; nt++)
            #pragma unroll
            for (int s = 0; s < 2; s++)
                c[nt][s][0] = c[nt][s][1] = c[nt][s][2] = c[nt][s][3] = 0.f;
        #pragma unroll
        for (int kcd = 0; kcd < 4; kcd++) {
            #pragma unroll
            for (int nt = 0; nt < 2; nt++) {
                const int nth = kc2 * 2 + nt;
                uint32_t q4[4];   // [bh0,bh1,bl0,bl1]
                *(uint4*)q4 = *(const uint4*)&KHb[((nth * 4 + kcd) * 32 + lane) * 4];
                mma_bf16(c[nt][0], AH[kcd], q4);
                mma_bf16(c[nt][1], AH[kcd], q4 + 2);
                mma_bf16(c[nt][1], AL[kcd], q4);
            }
        }
    };

    // ================= PASS 1: row sums (1-term QK, compacted 256-key tiles) =================
    float rs0 = 0.f, rs1 = 0.f;
    for (int bt = 0; bt < nt1; bt++) {
        const int cur = bt & 1;
        CP_WAIT0();
        __syncthreads();
        if (bt < nt1 - 1) { pfK1(cur ^ 1, bt + 1); CP_COMMIT(); }

        const uint32_t* KHb = smu + cur * 8192;

        #pragma unroll
        for (int kc2 = 0; kc2 < 16; kc2++) {
            float c[2][4];
            qk1(KHb, kc2, c);
            rs0 += ex2f(c[0][0] * C_SCALE) + ex2f(c[0][1] * C_SCALE)
                 + ex2f(c[1][0] * C_SCALE) + ex2f(c[1][1] * C_SCALE);
            rs1 += ex2f(c[0][2] * C_SCALE) + ex2f(c[0][3] * C_SCALE)
                 + ex2f(c[1][2] * C_SCALE) + ex2f(c[1][3] * C_SCALE);
        }
    }
    // pad correction: each zero-padded column contributed exp2(0)=1
    {
        int cnt = 0;
        const int lastb = (nt1 - 1) * 256;
        #pragma unroll
        for (int kc2 = 0; kc2 < 16; kc2++) {
            int p = lastb + kc2 * 16 + dlo;
            cnt += (p >= N) + (p + 1 >= N) + (p + 8 >= N) + (p + 9 >= N);
        }
        rs0 -= (float)cnt;
        rs1 -= (float)cnt;
    }
    rs0 += __shfl_xor_sync(0xffffffffu, rs0, 1);
    rs0 += __shfl_xor_sync(0xffffffffu, rs0, 2);
    rs1 += __shfl_xor_sync(0xffffffffu, rs1, 1);
    rs1 += __shfl_xor_sync(0xffffffffu, rs1, 2);
    const float li0 = -lg2f(rs0);
    const float li1 = -lg2f(rs1);

    // pass-1 buffers alias pass-2's KHL/VHL regions: retire pass-1 reads first
    __syncthreads();
    pfK(0, 0); pfV(0, 0); pfB(0, 0); CP_COMMIT();

    float accO[8][4];
    #pragma unroll
    for (int j = 0; j < 8; j++)
        accO[j][0] = accO[j][1] = accO[j][2] = accO[j][3] = 0.f;

    float* wr0 = W + ((size_t)bh * SQ + qt * MQ + qb + g) * SQ;
    float* wr1 = wr0 + (size_t)8 * SQ;

    // ================= PASS 2: W write + PV (dense, bias-folded mask) =================
    for (int kt = 0; kt < NTILE; kt++) {
        const int cur = kt & 1;
        CP_WAIT0();
        __syncthreads();
        if (kt < NTILE - 1) {
            pfK(cur ^ 1, kt + 1); pfV(cur ^ 1, kt + 1); pfB(cur ^ 1, kt + 1);
            CP_COMMIT();
        }

        const uint32_t* KHb = smu + U_KHL + cur * 4096;
        const uint32_t* VHb = smu + U_VHL + cur * 4096;
        const float* bbp = (const float*)(smu + U_BIA + cur * 64);
        const size_t ktb = (size_t)kt * TKEY;

        #pragma unroll
        for (int kc2 = 0; kc2 < 4; kc2++) {
            float c[2][2][4];
            qk3(KHb, kc2, c);

            int key0 = kc2 * 16 + dlo;
            float b0 = bbp[key0], b1 = bbp[key0 + 1], b2 = bbp[key0 + 8], b3 = bbp[key0 + 9];

            float e00 = ex2f(fmaf(c[0][0][0] + c[0][1][0], C_SCALE, li0 + b0));
            float e01 = ex2f(fmaf(c[0][0][1] + c[0][1][1], C_SCALE, li0 + b1));
            float e02 = ex2f(fmaf(c[0][0][2] + c[0][1][2], C_SCALE, li1 + b0));
            float e03 = ex2f(fmaf(c[0][0][3] + c[0][1][3], C_SCALE, li1 + b1));
            float e10 = ex2f(fmaf(c[1][0][0] + c[1][1][0], C_SCALE, li0 + b2));
            float e11 = ex2f(fmaf(c[1][0][1] + c[1][1][1], C_SCALE, li0 + b3));
            float e12 = ex2f(fmaf(c[1][0][2] + c[1][1][2], C_SCALE, li1 + b2));
            float e13 = ex2f(fmaf(c[1][0][3] + c[1][1][3], C_SCALE, li1 + b3));

            uint32_t aWH[4], aWL[4];
            split2(e00, e01, aWH[0], aWL[0]);
            split2(e02, e03, aWH[1], aWL[1]);
            split2(e10, e11, aWH[2], aWL[2]);
            split2(e12, e13, aWH[3], aWL[3]);

            #pragma unroll
            for (int ntd = 0; ntd < 8; ntd++) {
                uint32_t v4[4];   // [bh0,bh1,bl0,bl1]
                *(uint4*)v4 = *(const uint4*)&VHb[((kc2 * 8 + ntd) * 32 + lane) * 4];
                mma_bf16(accO[ntd], aWH, v4);
                mma_bf16(accO[ntd], aWL, v4);
                mma_bf16(accO[ntd], aWH, v4 + 2);
            }

            size_t cb = ktb + key0;
            stg_cs2(wr0 + cb,     e00, e01);
            stg_cs2(wr1 + cb,     e02, e03);
            stg_cs2(wr0 + cb + 8, e10, e11);
            stg_cs2(wr1 + cb + 8, e12, e13);
        }
    }

    // ---- output (warp-owned, direct) ----
    float* or0 = Out + ((size_t)bh * SQ + qt * MQ + qb + g) * DDIM + dlo;
    float* or1 = or0 + (size_t)8 * DDIM;
    #pragma unroll
    for (int ntd = 0; ntd < 8; ntd++) {
        stg_cs2(or0 + ntd * 8, accO[ntd][0], accO[ntd][1]);
        stg_cs2(or1 + ntd * 8, accO[ntd][2], accO[ntd][3]);
    }
}

extern "C" void kernel_launch(void* const* d_in, const int* in_sizes, int n_in,
                              void* d_out, int out_size) {
    const float* q = (const float*)d_in[0];
    const float* k = (const float*)d_in[1];
    const float* v = (const float*)d_in[2];
    const int*   m = (const int*)d_in[3];

    float* out = (float*)d_out;
    float* wts = out + (size_t)BB * HH * SQ * DDIM;

    prep_index<<<BB, 1024>>>(m);
    dim3 pgrid(BB * HH * 16, 3);
    prep_split<<<pgrid, 1024>>>(k, v);

    cudaFuncSetAttribute(attn16, cudaFuncAttributeMaxDynamicSharedMemorySize, SMEM_BYTES);
    dim3 grid(SQ / MQ, BB * HH);
    attn16<<<grid, NTH, SMEM_BYTES>>>(q, out, wts);
}

// round 17
// speedup vs baseline: 1.3814x; 1.0668x over previous
#include <cuda_runtime.h>
#include <cuda_bf16.h>
#include <cstdint>
#include <math.h>

#define BB 2
#define HH 16
#define SQ 2048
#define DDIM 64
#define MQ 128
#define TKEY 64
#define NTILE (SQ / TKEY)      // 32 (pass 2)
#define NTH 256
#define C_SCALE 0.18033688011110543f   // 0.125 * log2(e)
#define NEGB (-1250.0f)

// smem layout (u32 units)
#define U_KHL 0                // pass2 KHL [2][4096]; pass1 K1C [2][8192] spans KHL+VHL
#define U_VHL 8192             // pass2 VHL [2][4096]
#define U_BIA 16384            // [2][64] float (pass-2 bias)
#define U_QLO 16640            // [8 warps][4 kcd][32 lane][4] u32 = 4096 (Q-lo A-frags)
#define SMEM_BYTES (20736 * 4)

// global scratch
__device__ uint32_t g_K1C[32 * 16 * 4096];   // pass-1: COMPACTED hi-only, kcd-paired
__device__ uint32_t g_KHL[32 * 16 * 8192];   // pass-2: hi/lo interleaved K (dense)
__device__ uint32_t g_VHL[32 * 16 * 8192];   // pass-2: hi/lo interleaved V (dense)
__device__ int   g_idx[BB][SQ];
__device__ int   g_N[BB];
__device__ float g_bias[BB][SQ];

static __device__ __forceinline__ uint32_t smem_u32(const void* p) {
    uint32_t a;
    asm("{ .reg .u64 t; cvta.to.shared.u64 t, %1; cvt.u32.u64 %0, t; }" : "=r"(a) : "l"(p));
    return a;
}
static __device__ __forceinline__ void cp16(uint32_t dst, const void* src) {
    asm volatile("cp.async.cg.shared.global [%0], [%1], 16;" :: "r"(dst), "l"(src));
}
#define CP_COMMIT() asm volatile("cp.async.commit_group;" ::: "memory")
#define CP_WAIT0()  asm volatile("cp.async.wait_group 0;" ::: "memory")

static __device__ __forceinline__ float ex2f(float x) {
    float y; asm("ex2.approx.f32 %0, %1;" : "=f"(y) : "f"(x)); return y;
}
static __device__ __forceinline__ float lg2f(float x) {
    float y; asm("lg2.approx.f32 %0, %1;" : "=f"(y) : "f"(x)); return y;
}
static __device__ __forceinline__ void stg_cs2(float* p, float a, float b) {
    asm volatile("st.global.cs.v2.f32 [%0], {%1, %2};" :: "l"(p), "f"(a), "f"(b) : "memory");
}

static __device__ __forceinline__ void mma_bf16(float* c, const uint32_t* a, const uint32_t* b) {
    asm volatile(
        "mma.sync.aligned.m16n8k16.row.col.f32.bf16.bf16.f32 "
        "{%0,%1,%2,%3}, {%4,%5,%6,%7}, {%8,%9}, {%0,%1,%2,%3};"
        : "+f"(c[0]), "+f"(c[1]), "+f"(c[2]), "+f"(c[3])
        : "r"(a[0]), "r"(a[1]), "r"(a[2]), "r"(a[3]), "r"(b[0]), "r"(b[1]));
}

static __device__ __forceinline__ void split2(float a, float b, uint32_t& hi, uint32_t& lo) {
    __nv_bfloat162 h = __floats2bfloat162_rn(a, b);
    float ra = a - __bfloat162float(__low2bfloat16(h));
    float rb = b - __bfloat162float(__high2bfloat16(h));
    __nv_bfloat162 l = __floats2bfloat162_rn(ra, rb);
    hi = *reinterpret_cast<uint32_t*>(&h);
    lo = *reinterpret_cast<uint32_t*>(&l);
}

// ---------- prep A: compacted index + bias + count per batch ----------
__global__ __launch_bounds__(1024)
void prep_index(const int* __restrict__ M) {
    const int b = blockIdx.x;
    const int t = threadIdx.x;
    __shared__ int a[1024];
    int m0 = M[b * SQ + 2 * t];
    int m1 = M[b * SQ + 2 * t + 1];
    g_bias[b][2 * t]     = m0 ? 0.f : NEGB;
    g_bias[b][2 * t + 1] = m1 ? 0.f : NEGB;
    a[t] = m0 + m1;
    __syncthreads();
    for (int off = 1; off < 1024; off <<= 1) {
        int v = a[t];
        if (t >= off) v += a[t - off];
        __syncthreads();
        a[t] = v;
        __syncthreads();
    }
    int total = a[1023];
    int excl = a[t] - (m0 + m1);
    if (m0) g_idx[b][excl] = 2 * t;
    if (m1) g_idx[b][excl + m0] = 2 * t + 1;
    for (int i = t; i < SQ; i += 1024)
        if (i >= total) g_idx[b][i] = -1;
    if (t == 0) g_N[b] = total;
}

// ---------- prep B (fused): dense K, dense V, compacted K ----------
__global__ __launch_bounds__(1024)
void prep_split(const float* __restrict__ K, const float* __restrict__ V) {
    const int tile = blockIdx.x;               // bh*16 + 128-key tile
    const int t = threadIdx.x;
    const size_t base = (size_t)tile * 128 * DDIM;
    if (blockIdx.y == 0) {
        const float2* src = (const float2*)(K + base);
        uint32_t* dI = g_KHL + (size_t)tile * 8192;
        #pragma unroll
        for (int i = 0; i < 4; i++) {
            int idx = i * 1024 + t;
            int key = idx >> 5, dp = idx & 31;
            float2 x = src[idx];
            uint32_t hi, lo; split2(x.x, x.y, hi, lo);
            int nt = key >> 3, kcd = dp >> 3;
            int lane = (key & 7) * 4 + (dp & 3);
            int r = (dp >> 2) & 1;
            int iq = ((nt * 4 + kcd) * 32 + lane) * 4;
            dI[iq + r] = hi;
            dI[iq + 2 + r] = lo;
        }
    } else if (blockIdx.y == 1) {
        const float* src = V + base;
        uint32_t* dI = g_VHL + (size_t)tile * 8192;
        #pragma unroll
        for (int i = 0; i < 4; i++) {
            int idx = i * 1024 + t;
            int d = idx & 63, kp = idx >> 6;
            float va = src[(size_t)(2 * kp) * DDIM + d];
            float vb = src[(size_t)(2 * kp + 1) * DDIM + d];
            uint32_t hi, lo; split2(va, vb, hi, lo);
            int kc2 = kp >> 3, w8 = kp & 7;
            int ntd = d >> 3;
            int lane = (d & 7) * 4 + (w8 & 3);
            int r = w8 >> 2;
            int iq = ((kc2 * 8 + ntd) * 32 + lane) * 4;
            dI[iq + r] = hi;
            dI[iq + 2 + r] = lo;
        }
    } else {
        // compacted hi-only K for pass 1
        const int bh = tile >> 4;
        const int b  = bh / HH;
        const int tloc = tile & 15;
        uint32_t* d1 = g_K1C + (size_t)tile * 4096;
        #pragma unroll
        for (int i = 0; i < 4; i++) {
            int idx = i * 1024 + t;
            int key = idx >> 5, dp = idx & 31;
            int orig = g_idx[b][tloc * 128 + key];
            float2 x = make_float2(0.f, 0.f);
            if (orig >= 0)
                x = ((const float2*)(K + ((size_t)bh * SQ + orig) * DDIM))[dp];
            __nv_bfloat162 h = __floats2bfloat162_rn(x.x, x.y);
            int nt = key >> 3, kcd = dp >> 3;
            int lane = (key & 7) * 4 + (dp & 3);
            int r = (dp >> 2) & 1;
            d1[((nt * 2 + (kcd >> 1)) * 32 + lane) * 4 + (kcd & 1) * 2 + r] =
                *reinterpret_cast<uint32_t*>(&h);
        }
    }
}

// ---------- main attention kernel: 8 warps, 2 CTAs/SM ----------
__global__ __launch_bounds__(NTH, 2)
void attn17(const float* __restrict__ Q,
            float* __restrict__ Out, float* __restrict__ W) {
    extern __shared__ __align__(16) uint32_t smu[];
    const uint32_t sb = smem_u32(smu);

    const int t    = threadIdx.x;
    const int lane = t & 31;
    const int wid  = t >> 5;
    const int g    = lane >> 2;
    const int t4   = lane & 3;
    const int dlo  = 2 * t4;
    const int qb   = wid * 16;

    const int qt = blockIdx.x;
    const int bh = blockIdx.y;
    const int b  = bh / HH;

    const float* qg = Q + ((size_t)bh * SQ + (size_t)qt * MQ) * DDIM;
    const int N = g_N[b];
    const int nt1 = (N + 255) >> 8;            // compacted pass-1 256-key tiles

    // ---- pass-1 prefetcher: compacted 256-key tiles ----
    auto pfK1 = [&](int buf, int bt) {
        const uint32_t* s = g_K1C + ((size_t)bh * 16 + bt * 2) * 4096;
        const uint32_t d = sb + (uint32_t)buf * 8192 * 4;
        #pragma unroll
        for (int c = 0; c < 8; c++) {
            int o = (c * NTH + t) * 4;
            cp16(d + o * 4, s + o);
        }
    };
    // ---- pass-2 prefetchers ----
    auto pfK = [&](int buf, int kt64) {
        const size_t off = ((size_t)bh * 16 + (kt64 >> 1)) * 8192 + (size_t)(kt64 & 1) * 4096;
        const uint32_t d = sb + (U_KHL + buf * 4096) * 4;
        #pragma unroll
        for (int c = 0; c < 4; c++) {
            int o = (c * NTH + t) * 4;
            cp16(d + o * 4, g_KHL + off + o);
        }
    };
    auto pfV = [&](int buf, int kt64) {
        const size_t off = ((size_t)bh * 16 + (kt64 >> 1)) * 8192 + (size_t)(kt64 & 1) * 4096;
        const uint32_t d = sb + (U_VHL + buf * 4096) * 4;
        #pragma unroll
        for (int c = 0; c < 4; c++) {
            int o = (c * NTH + t) * 4;
            cp16(d + o * 4, g_VHL + off + o);
        }
    };
    auto pfB = [&](int buf, int kt64) {
        if (t < 16) cp16(sb + (U_BIA + buf * 64 + t * 4) * 4, &g_bias[b][kt64 * TKEY + t * 4]);
    };

    pfK1(0, 0); CP_COMMIT();

    // ---- persistent Q A-fragments: hi in regs, lo in (warp-private) smem ----
    uint32_t AH[4][4];
    uint32_t* QLOw = smu + U_QLO + wid * 512;   // [kcd][lane][4]
    #pragma unroll
    for (int kc = 0; kc < 4; kc++) {
        const float* r0 = qg + (size_t)(qb + g) * DDIM + kc * 16 + dlo;
        const float* r1 = r0 + 8 * DDIM;
        float2 p0 = *(const float2*)(r0);
        float2 p1 = *(const float2*)(r1);
        float2 p2 = *(const float2*)(r0 + 8);
        float2 p3 = *(const float2*)(r1 + 8);
        uint32_t al[4];
        split2(p0.x, p0.y, AH[kc][0], al[0]);
        split2(p1.x, p1.y, AH[kc][1], al[1]);
        split2(p2.x, p2.y, AH[kc][2], al[2]);
        split2(p3.x, p3.y, AH[kc][3], al[3]);
        *(uint4*)&QLOw[(kc * 32 + lane) * 4] = *(uint4*)al;
    }

    // pass-1 QK (1-term, kcd-paired LDS.128, 256-key tile addressing)
    auto qk1 = [&](const uint32_t* KHb, int kc2, float (&c)[2][4]) {
        #pragma unroll
        for (int nt = 0; nt < 2; nt++)
            c[nt][0] = c[nt][1] = c[nt][2] = c[nt][3] = 0.f;
        #pragma unroll
        for (int nt = 0; nt < 2; nt++) {
            const int ntg = kc2 * 2 + nt;
            const int blk = (ntg >> 4) * 4096;
            const int ntl = ntg & 15;
            #pragma unroll
            for (int p = 0; p < 2; p++) {
                uint32_t q4[4];
                *(uint4*)q4 = *(const uint4*)&KHb[blk + ((ntl * 2 + p) * 32 + lane) * 4];
                mma_bf16(c[nt], AH[2 * p],     q4);
                mma_bf16(c[nt], AH[2 * p + 1], q4 + 2);
            }
        }
    };
    // pass-2 QK (3-term, interleaved LDS.128, AL from smem)
    auto qk3 = [&](const uint32_t* KHb, int kc2, float (&c)[2][2][4]) {
        #pragma unroll
        for (int nt = 0; nt < 2; nt++)
            #pragma unroll
            for (int s = 0; s < 2; s++)
                c[nt][s][0] = c[nt][s][1] = c[nt][s][2] = c[nt][s][3] = 0.f;
        #pragma unroll
        for (int kcd = 0; kcd < 4; kcd++) {
            uint32_t al4[4];
            *(uint4*)al4 = *(const uint4*)&QLOw[(kcd * 32 + lane) * 4];
            #pragma unroll
            for (int nt = 0; nt < 2; nt++) {
                const int nth = kc2 * 2 + nt;
                uint32_t q4[4];   // [bh0,bh1,bl0,bl1]
                *(uint4*)q4 = *(const uint4*)&KHb[((nth * 4 + kcd) * 32 + lane) * 4];
                mma_bf16(c[nt][0], AH[kcd], q4);
                mma_bf16(c[nt][1], AH[kcd], q4 + 2);
                mma_bf16(c[nt][1], al4, q4);
            }
        }
    };

    // ================= PASS 1: row sums (1-term QK, compacted, lookahead) =================
    float rs0 = 0.f, rs1 = 0.f;
    for (int bt = 0; bt < nt1; bt++) {
        const int cur = bt & 1;
        CP_WAIT0();
        __syncthreads();
        if (bt < nt1 - 1) { pfK1(cur ^ 1, bt + 1); CP_COMMIT(); }

        const uint32_t* KHb = smu + cur * 8192;

        float c1[2][2][4];
        qk1(KHb, 0, c1[0]);
        #pragma unroll
        for (int kc2 = 0; kc2 < 16; kc2++) {
            if (kc2 < 15) qk1(KHb, kc2 + 1, c1[(kc2 + 1) & 1]);
            float (&c)[2][4] = c1[kc2 & 1];
            rs0 += ex2f(c[0][0] * C_SCALE) + ex2f(c[0][1] * C_SCALE)
                 + ex2f(c[1][0] * C_SCALE) + ex2f(c[1][1] * C_SCALE);
            rs1 += ex2f(c[0][2] * C_SCALE) + ex2f(c[0][3] * C_SCALE)
                 + ex2f(c[1][2] * C_SCALE) + ex2f(c[1][3] * C_SCALE);
        }
    }
    // pad correction: each zero-padded column contributed exp2(0)=1
    {
        int cnt = 0;
        const int lastb = (nt1 - 1) * 256;
        #pragma unroll
        for (int kc2 = 0; kc2 < 16; kc2++) {
            int p = lastb + kc2 * 16 + dlo;
            cnt += (p >= N) + (p + 1 >= N) + (p + 8 >= N) + (p + 9 >= N);
        }
        rs0 -= (float)cnt;
        rs1 -= (float)cnt;
    }
    rs0 += __shfl_xor_sync(0xffffffffu, rs0, 1);
    rs0 += __shfl_xor_sync(0xffffffffu, rs0, 2);
    rs1 += __shfl_xor_sync(0xffffffffu, rs1, 1);
    rs1 += __shfl_xor_sync(0xffffffffu, rs1, 2);
    const float li0 = -lg2f(rs0);
    const float li1 = -lg2f(rs1);

    // pass-1 buffers alias pass-2's KHL/VHL regions: retire pass-1 reads first
    __syncthreads();
    pfK(0, 0); pfV(0, 0); pfB(0, 0); CP_COMMIT();

    float accO[8][4];
    #pragma unroll
    for (int j = 0; j < 8; j++)
        accO[j][0] = accO[j][1] = accO[j][2] = accO[j][3] = 0.f;

    float* wr0 = W + ((size_t)bh * SQ + qt * MQ + qb + g) * SQ;
    float* wr1 = wr0 + (size_t)8 * SQ;

    // ================= PASS 2: W write + PV (dense, bias mask, kc2 lookahead) =================
    for (int kt = 0; kt < NTILE; kt++) {
        const int cur = kt & 1;
        CP_WAIT0();
        __syncthreads();
        if (kt < NTILE - 1) {
            pfK(cur ^ 1, kt + 1); pfV(cur ^ 1, kt + 1); pfB(cur ^ 1, kt + 1);
            CP_COMMIT();
        }

        const uint32_t* KHb = smu + U_KHL + cur * 4096;
        const uint32_t* VHb = smu + U_VHL + cur * 4096;
        const float* bbp = (const float*)(smu + U_BIA + cur * 64);
        const size_t ktb = (size_t)kt * TKEY;

        float cb[2][2][2][4];
        qk3(KHb, 0, cb[0]);
        #pragma unroll
        for (int kc2 = 0; kc2 < 4; kc2++) {
            if (kc2 < 3) qk3(KHb, kc2 + 1, cb[(kc2 + 1) & 1]);
            float (&c)[2][2][4] = cb[kc2 & 1];

            int key0 = kc2 * 16 + dlo;
            float b0 = bbp[key0], b1 = bbp[key0 + 1], b2 = bbp[key0 + 8], b3 = bbp[key0 + 9];

            float e00 = ex2f(fmaf(c[0][0][0] + c[0][1][0], C_SCALE, li0 + b0));
            float e01 = ex2f(fmaf(c[0][0][1] + c[0][1][1], C_SCALE, li0 + b1));
            float e02 = ex2f(fmaf(c[0][0][2] + c[0][1][2], C_SCALE, li1 + b0));
            float e03 = ex2f(fmaf(c[0][0][3] + c[0][1][3], C_SCALE, li1 + b1));
            float e10 = ex2f(fmaf(c[1][0][0] + c[1][1][0], C_SCALE, li0 + b2));
            float e11 = ex2f(fmaf(c[1][0][1] + c[1][1][1], C_SCALE, li0 + b3));
            float e12 = ex2f(fmaf(c[1][0][2] + c[1][1][2], C_SCALE, li1 + b2));
            float e13 = ex2f(fmaf(c[1][0][3] + c[1][1][3], C_SCALE, li1 + b3));

            size_t cbo = ktb + key0;
            stg_cs2(wr0 + cbo,     e00, e01);
            stg_cs2(wr1 + cbo,     e02, e03);
            stg_cs2(wr0 + cbo + 8, e10, e11);
            stg_cs2(wr1 + cbo + 8, e12, e13);

            uint32_t aWH[4], aWL[4];
            split2(e00, e01, aWH[0], aWL[0]);
            split2(e02, e03, aWH[1], aWL[1]);
            split2(e10, e11, aWH[2], aWL[2]);
            split2(e12, e13, aWH[3], aWL[3]);

            #pragma unroll
            for (int ntd = 0; ntd < 8; ntd++) {
                uint32_t v4[4];   // [bh0,bh1,bl0,bl1]
                *(uint4*)v4 = *(const uint4*)&VHb[((kc2 * 8 + ntd) * 32 + lane) * 4];
                mma_bf16(accO[ntd], aWH, v4);
                mma_bf16(accO[ntd], aWL, v4);
                mma_bf16(accO[ntd], aWH, v4 + 2);
            }
        }
    }

    // ---- output (warp-owned, direct) ----
    float* or0 = Out + ((size_t)bh * SQ + qt * MQ + qb + g) * DDIM + dlo;
    float* or1 = or0 + (size_t)8 * DDIM;
    #pragma unroll
    for (int ntd = 0; ntd < 8; ntd++) {
        stg_cs2(or0 + ntd * 8, accO[ntd][0], accO[ntd][1]);
        stg_cs2(or1 + ntd * 8, accO[ntd][2], accO[ntd][3]);
    }
}

extern "C" void kernel_launch(void* const* d_in, const int* in_sizes, int n_in,
                              void* d_out, int out_size) {
    const float* q = (const float*)d_in[0];
    const float* k = (const float*)d_in[1];
    const float* v = (const float*)d_in[2];
    const int*   m = (const int*)d_in[3];

    float* out = (float*)d_out;
    float* wts = out + (size_t)BB * HH * SQ * DDIM;

    prep_index<<<BB, 1024>>>(m);
    dim3 pgrid(BB * HH * 16, 3);
    prep_split<<<pgrid, 1024>>>(k, v);

    cudaFuncSetAttribute(attn17, cudaFuncAttributeMaxDynamicSharedMemorySize, SMEM_BYTES);
    dim3 grid(SQ / MQ, BB * HH);
    attn17<<<grid, NTH, SMEM_BYTES>>>(q, out, wts);
}